// round 10
// baseline (speedup 1.0000x reference)
#include <cuda_runtime.h>
#include <cuda_fp16.h>
#include <cstdint>

#define ZDIM   128
#define MDIM   8192
#define NB     128
#define MT     64                    // M rows per CTA
#define NCTA   (MDIM / MT)           // 128 CTAs
#define KT     64                    // K per tile (fp16 tile row = 128B)
#define NITER  (MDIM / KT)           // 128
#define STAGES 8
#define BT_BYTES   (MT * 128)        // 8 KB fp16 B tile
#define RING_BYTES (STAGES * BT_BYTES)        // 64 KB
#define FULL_OFF   RING_BYTES
#define EMPTY_OFF  (RING_BYTES + 64)
#define SS_OFF     (RING_BYTES + 128)
#define SMEM_DYN   (RING_BYTES + 2048)
#define OUT_PLANE  (NB * MDIM)

// eps packed into m16n8k16 B-fragment layout, fp16 (2 MB + 64 KB tail pad for
// harmless out-of-range prefetch).
// uint4 index: (kc*8 + nP)*32 + lane ; kc = k/16 (0..511), nP = n/16 (0..7)
__device__ __align__(16) __half2 g_epsh[OUT_PLANE / 2 + 32768];

static __device__ __forceinline__ uint32_t smem_u32(const void* p) {
    uint32_t a;
    asm("{ .reg .u64 t; cvta.to.shared.u64 t, %1; cvt.u32.u64 %0, t; }" : "=r"(a) : "l"(p));
    return a;
}

#define MBAR_INIT(a, c)  asm volatile("mbarrier.init.shared.b64 [%0], %1;" :: "r"((uint32_t)(a)), "r"((uint32_t)(c)) : "memory")
#define MBAR_ARRIVE(a)   asm volatile("mbarrier.arrive.shared.b64 _, [%0];" :: "r"((uint32_t)(a)) : "memory")

#define MBAR_WAIT(a, ph) do {                                                      \
    uint32_t _m = (uint32_t)(a), _p = (uint32_t)(ph);                              \
    asm volatile("{\n\t.reg .pred P;\n\t"                                          \
        "WL_%=:\n\t"                                                               \
        "mbarrier.try_wait.parity.acquire.cta.shared::cta.b64 P, [%0], %1, 0x989680;\n\t" \
        "@P bra.uni WD_%=;\n\t"                                                    \
        "bra.uni WL_%=;\n\t"                                                       \
        "WD_%=:\n\t}" :: "r"(_m), "r"(_p) : "memory");                             \
} while (0)

#define LDSM_X4(r, addr) \
    asm volatile("ldmatrix.sync.aligned.m8n8.x4.shared.b16 {%0,%1,%2,%3}, [%4];" \
        : "=r"((r)[0]), "=r"((r)[1]), "=r"((r)[2]), "=r"((r)[3]) : "r"((uint32_t)(addr)))

#define MMA16(d, a, b0, b1) \
    asm volatile("mma.sync.aligned.m16n8k16.row.col.f32.f16.f16.f32 " \
        "{%0,%1,%2,%3}, {%4,%5,%6,%7}, {%8,%9}, {%0,%1,%2,%3};" \
        : "+f"((d)[0]), "+f"((d)[1]), "+f"((d)[2]), "+f"((d)[3]) \
        : "r"((a)[0]), "r"((a)[1]), "r"((a)[2]), "r"((a)[3]), "r"(b0), "r"(b1))

// ---------------------------------------------------------------------------
__global__ void cov_fill(const float* __restrict__ mu, const float* __restrict__ logstd,
                         const float* __restrict__ eps, float* __restrict__ out) {
    int i = blockIdx.x * blockDim.x + threadIdx.x;
    if (i >= OUT_PLANE) return;
    int z = i & (ZDIM - 1);
    out[i] = mu[z];
    out[OUT_PLANE + i] = 2.0f * logstd[z];
    if (i < OUT_PLANE / 2) {
        int q  = i & 3;
        int l  = (i >> 2) & 31;
        int nP = (i >> 7) & 7;
        int kc = i >> 10;
        int n  = (2 * nP + (q >> 1)) * 8 + (l >> 2);
        int k  = kc * 16 + 2 * (l & 3) + 8 * (q & 1);
        g_epsh[i] = __floats2half2_rn(eps[(size_t)n * MDIM + k], eps[(size_t)n * MDIM + k + 1]);
    }
}

// ---------------------------------------------------------------------------
// 128 CTAs x 384 threads.
// warps 0-7: compute; warp = kpar(wid>>2) x mq((wid>>1)&1) x nh(wid&1); M32xN64.
//            eps fragments LDG'd from L2 (g_epsh) via a 4-deep register ring
//            (prefetch distance = one full K-tile > L2 latency).
// warps 8-11: producers — triple-buffered (distance-2) LDG of fp32 B ->
//             cvt fp16 (+fp32 sumsq) -> STS.
// ---------------------------------------------------------------------------
__global__ void __launch_bounds__(384, 1) cov_main(
    const float* __restrict__ B, const float* __restrict__ mu,
    const float* __restrict__ logstd, float* __restrict__ out)
{
    extern __shared__ char smem_raw[];
    const uint32_t raw  = smem_u32(smem_raw);
    const uint32_t base = (raw + 1023u) & ~1023u;
    char* basep = smem_raw + (base - raw);
    float* ssp   = (float*)(basep + SS_OFF);
    float* smemC = (float*)basep;              // reused after main loop (32 KB)

    const int tid  = threadIdx.x;
    const int wid  = tid >> 5;
    const int lane = tid & 31;

    if (tid == 0) {
        #pragma unroll
        for (int s = 0; s < STAGES; s++) {
            MBAR_INIT(base + FULL_OFF  + s * 8, 128);  // 128 producer threads
            MBAR_INIT(base + EMPTY_OFF + s * 8, 4);    // lane0 of 4 consuming warps
        }
    }
    if (tid < MT) ssp[tid] = 0.0f;
    __syncthreads();

    float C[2][8][4];
    const int kpar = wid >> 2;
    const int mq   = (wid >> 1) & 1;
    const int nh   = wid & 1;
    const int g    = lane >> 2;
    const int tg   = lane & 3;

    if (wid < 8) {
        // ---------------- compute warps ----------------
        const uint32_t rowpat = (uint32_t)((lane & 7) + 8 * ((lane >> 3) & 1));
        const uint32_t swzl   = (uint32_t)(lane & 7) << 4;
        uint32_t aRow[2], colA[4];
        #pragma unroll
        for (int q = 0; q < 2; q++)
            aRow[q] = ((uint32_t)(mq * 32 + q * 16) + rowpat) * 128u;
        #pragma unroll
        for (int sk = 0; sk < 4; sk++)
            colA[sk] = ((uint32_t)(sk * 32 + 16 * (lane >> 4))) ^ swzl;

        #pragma unroll
        for (int q = 0; q < 2; q++)
            #pragma unroll
            for (int j = 0; j < 8; j++)
                #pragma unroll
                for (int e = 0; e < 4; e++) C[q][j][e] = 0.0f;

        const uint4* epsp = (const uint4*)g_epsh;
        // eps fragment: idx(kc, jp) = (kc*8 + nh*4 + jp)*32 + lane
        #define EIDX(KC, JP) ((size_t)(((KC) * 8 + nh * 4 + (JP)) * 32 + lane))
        // 4-deep ring: bb[sk] holds the fragment for the current tile's sk step.
        uint4 bb[4][4];
        {
            const int kc0 = kpar * 4;
            #pragma unroll
            for (int j = 0; j < 4; j++)
                #pragma unroll
                for (int jp = 0; jp < 4; jp++)
                    bb[j][jp] = __ldg(&epsp[EIDX(kc0 + j, jp)]);
        }

        for (int ti = 0; ti < NITER / 2; ti++) {
            const int it = 2 * ti + kpar;
            const int s  = it & (STAGES - 1);
            const int ph = (it >> 3) & 1;
            MBAR_WAIT(base + FULL_OFF + s * 8, ph);
            const uint32_t stg = base + (uint32_t)s * BT_BYTES;
            const int kcN = (it + 2) * 4;            // refill target tile

            #pragma unroll
            for (int sk = 0; sk < 4; sk++) {
                uint32_t a[2][4];
                #pragma unroll
                for (int q = 0; q < 2; q++)
                    LDSM_X4(a[q], stg + aRow[q] + colA[sk]);
                #pragma unroll
                for (int jp = 0; jp < 4; jp++)
                    #pragma unroll
                    for (int q = 0; q < 2; q++) {
                        MMA16(C[q][2 * jp    ], a[q], bb[sk][jp].x, bb[sk][jp].y);
                        MMA16(C[q][2 * jp + 1], a[q], bb[sk][jp].z, bb[sk][jp].w);
                    }
                // refill for the NEXT tile of this parity (distance = 4 sk bodies)
                #pragma unroll
                for (int jp = 0; jp < 4; jp++)
                    bb[sk][jp] = __ldg(&epsp[EIDX(kcN + sk, jp)]);
            }
            __syncwarp();
            if (lane == 0) MBAR_ARRIVE(base + EMPTY_OFF + s * 8);
        }
        #undef EIDX
    } else {
        // ---------------- producer warps (128 threads) ----------------
        const int p  = tid - 256;                 // 0..127
        const int rb = p >> 4;                    // base row 0..7
        const int cc = p & 15;                    // 16B fp32 chunk within 256B row
        const float* gB = B + (size_t)blockIdx.x * MT * MDIM;

        float4 bA[8], bB[8], bC[8];
        float ss[8];
        #pragma unroll
        for (int i = 0; i < 8; i++) ss[i] = 0.0f;

        #define P_HANDLE(IT, BUF) do {                                              \
            const int _it = (IT);                                                   \
            const int _s  = _it & (STAGES - 1);                                     \
            const int _ph = ((_it >> 3) & 1) ^ 1;                                   \
            MBAR_WAIT(base + EMPTY_OFF + _s * 8, _ph);                              \
            const float* _src = gB + (size_t)_it * KT + cc * 4;                     \
            _Pragma("unroll")                                                       \
            for (int u = 0; u < 8; u++)                                             \
                (BUF)[u] = *(const float4*)(_src + (size_t)(rb + 8 * u) * MDIM);    \
        } while (0)

        #define P_FLUSH(JT, BUF) do {                                               \
            const int _jt = (JT);                                                   \
            const uint32_t _stgj = base + (uint32_t)(_jt & (STAGES - 1)) * BT_BYTES; \
            _Pragma("unroll")                                                       \
            for (int u = 0; u < 8; u++) {                                           \
                const int _row = rb + 8 * u;                                        \
                float4 _f = (BUF)[u];                                               \
                __half2 _h0 = __floats2half2_rn(_f.x, _f.y);                        \
                __half2 _h1 = __floats2half2_rn(_f.z, _f.w);                        \
                const uint32_t _a = _stgj + (uint32_t)_row * 128u                   \
                    + (((uint32_t)(cc * 8)) ^ ((uint32_t)(_row & 7) << 4));         \
                asm volatile("st.shared.v2.b32 [%0], {%1, %2};"                     \
                    :: "r"(_a), "r"(*(uint32_t*)&_h0), "r"(*(uint32_t*)&_h1) : "memory"); \
                ss[u] = fmaf(_f.x, _f.x, ss[u]);                                    \
                ss[u] = fmaf(_f.y, _f.y, ss[u]);                                    \
                ss[u] = fmaf(_f.z, _f.z, ss[u]);                                    \
                ss[u] = fmaf(_f.w, _f.w, ss[u]);                                    \
            }                                                                       \
            MBAR_ARRIVE(base + FULL_OFF + (_jt & (STAGES - 1)) * 8);                \
        } while (0)

        // distance-2 pipeline: H(k+2) issues before F(k); buffers rotate mod 3
        P_HANDLE(0, bA);
        P_HANDLE(1, bB);
        for (int j = 0; j < (NITER - 2) / 3; j++) {      // 42 iterations -> F(0..125)
            P_HANDLE(3 * j + 2, bC); P_FLUSH(3 * j,     bA);
            P_HANDLE(3 * j + 3, bA); P_FLUSH(3 * j + 1, bB);
            P_HANDLE(3 * j + 4, bB); P_FLUSH(3 * j + 2, bC);
        }
        P_FLUSH(NITER - 2, bA);
        P_FLUSH(NITER - 1, bB);

        // sumsq: reduce over the 16 column-chunk lanes of each row
        #pragma unroll
        for (int u = 0; u < 8; u++) {
            float v = ss[u];
            v += __shfl_xor_sync(0xffffffffu, v, 1);
            v += __shfl_xor_sync(0xffffffffu, v, 2);
            v += __shfl_xor_sync(0xffffffffu, v, 4);
            v += __shfl_xor_sync(0xffffffffu, v, 8);
            if (cc == 0) atomicAdd(&ssp[rb + 8 * u], v);
        }
    }

    __syncthreads();                 // main-loop smem use done; ring reusable

    // kpar 0 warps store C into smemC[col*64 + row]
    if (wid < 4) {
        #pragma unroll
        for (int q = 0; q < 2; q++)
            #pragma unroll
            for (int j = 0; j < 8; j++) {
                int col = nh * 64 + j * 8 + 2 * tg;
                int row = mq * 32 + q * 16 + g;
                smemC[(col    ) * 64 + row    ] = C[q][j][0];
                smemC[(col + 1) * 64 + row    ] = C[q][j][1];
                smemC[(col    ) * 64 + row + 8] = C[q][j][2];
                smemC[(col + 1) * 64 + row + 8] = C[q][j][3];
            }
    }
    __syncthreads();
    // kpar 1 warps accumulate
    if (wid >= 4 && wid < 8) {
        #pragma unroll
        for (int q = 0; q < 2; q++)
            #pragma unroll
            for (int j = 0; j < 8; j++) {
                int col = nh * 64 + j * 8 + 2 * tg;
                int row = mq * 32 + q * 16 + g;
                smemC[(col    ) * 64 + row    ] += C[q][j][0];
                smemC[(col + 1) * 64 + row    ] += C[q][j][1];
                smemC[(col    ) * 64 + row + 8] += C[q][j][2];
                smemC[(col + 1) * 64 + row + 8] += C[q][j][3];
            }
    }
    __syncthreads();

    if (tid < 128) {
        int m = tid & 63, bh = tid >> 6;
        int mg = blockIdx.x * MT + m, z = mg & (ZDIM - 1);
        float sc  = rsqrtf(ssp[m]) * expf(logstd[z]);
        float muv = mu[z];
        float* op = out + 2 * (size_t)OUT_PLANE + mg;
        #pragma unroll 4
        for (int b = bh * 64; b < bh * 64 + 64; b++)
            op[(size_t)b * MDIM] = fmaf(sc, smemC[b * 64 + m], muv);
    }
}

extern "C" void kernel_launch(void* const* d_in, const int* in_sizes, int n_in,
                              void* d_out, int out_size) {
    const float* mu     = (const float*)d_in[0];
    const float* logstd = (const float*)d_in[1];
    const float* B      = (const float*)d_in[2];
    const float* eps    = (const float*)d_in[3];
    float* out = (float*)d_out;

    cudaFuncSetAttribute(cov_main, cudaFuncAttributeMaxDynamicSharedMemorySize, SMEM_DYN);

    cov_fill<<<(OUT_PLANE + 511) / 512, 512>>>(mu, logstd, eps, out);
    cov_main<<<NCTA, 384, SMEM_DYN>>>(B, mu, logstd, out);
}

// round 12
// speedup vs baseline: 1.0810x; 1.0810x over previous
#include <cuda_runtime.h>
#include <cuda_fp16.h>
#include <cstdint>

#define ZDIM   128
#define MDIM   8192
#define NB     128
#define MT     32                    // M rows per CTA
#define NCTA   (MDIM / MT)           // 256 CTAs
#define KT     64                    // K per tile (fp16 tile row = 128B)
#define NITER  (MDIM / KT)           // 128
#define STAGES 8
#define BT_BYTES   (MT * 128)        // 4 KB fp16 B tile
#define RING_BYTES (STAGES * BT_BYTES)        // 32 KB
#define FULL_OFF   RING_BYTES
#define EMPTY_OFF  (RING_BYTES + 64)
#define SS_OFF     (RING_BYTES + 128)
#define SMEM_DYN   (RING_BYTES + 2048)        // 34.8 KB -> 2 CTAs/SM fits easily
#define OUT_PLANE  (NB * MDIM)

// eps packed into m16n8k16 B-fragment layout, fp16 (2 MB + 128 KB tail pad for
// harmless out-of-range prefetch).
// uint4 index: (kc*8 + nP)*32 + lane ; kc = k/16 (0..511), nP = n/16 (0..7)
__device__ __align__(16) __half2 g_epsh[OUT_PLANE / 2 + 65536];

static __device__ __forceinline__ uint32_t smem_u32(const void* p) {
    uint32_t a;
    asm("{ .reg .u64 t; cvta.to.shared.u64 t, %1; cvt.u32.u64 %0, t; }" : "=r"(a) : "l"(p));
    return a;
}

#define MBAR_INIT(a, c)  asm volatile("mbarrier.init.shared.b64 [%0], %1;" :: "r"((uint32_t)(a)), "r"((uint32_t)(c)) : "memory")
#define MBAR_ARRIVE(a)   asm volatile("mbarrier.arrive.shared.b64 _, [%0];" :: "r"((uint32_t)(a)) : "memory")

#define MBAR_WAIT(a, ph) do {                                                      \
    uint32_t _m = (uint32_t)(a), _p = (uint32_t)(ph);                              \
    asm volatile("{\n\t.reg .pred P;\n\t"                                          \
        "WL_%=:\n\t"                                                               \
        "mbarrier.try_wait.parity.acquire.cta.shared::cta.b64 P, [%0], %1, 0x989680;\n\t" \
        "@P bra.uni WD_%=;\n\t"                                                    \
        "bra.uni WL_%=;\n\t"                                                       \
        "WD_%=:\n\t}" :: "r"(_m), "r"(_p) : "memory");                             \
} while (0)

#define LDSM_X4(r, addr) \
    asm volatile("ldmatrix.sync.aligned.m8n8.x4.shared.b16 {%0,%1,%2,%3}, [%4];" \
        : "=r"((r)[0]), "=r"((r)[1]), "=r"((r)[2]), "=r"((r)[3]) : "r"((uint32_t)(addr)))

#define MMA16(d, a, b0, b1) \
    asm volatile("mma.sync.aligned.m16n8k16.row.col.f32.f16.f16.f32 " \
        "{%0,%1,%2,%3}, {%4,%5,%6,%7}, {%8,%9}, {%0,%1,%2,%3};" \
        : "+f"((d)[0]), "+f"((d)[1]), "+f"((d)[2]), "+f"((d)[3]) \
        : "r"((a)[0]), "r"((a)[1]), "r"((a)[2]), "r"((a)[3]), "r"(b0), "r"(b1))

// ---------------------------------------------------------------------------
__global__ void cov_fill(const float* __restrict__ mu, const float* __restrict__ logstd,
                         const float* __restrict__ eps, float* __restrict__ out) {
    int i = blockIdx.x * blockDim.x + threadIdx.x;
    if (i >= OUT_PLANE) return;
    int z = i & (ZDIM - 1);
    out[i] = mu[z];
    out[OUT_PLANE + i] = 2.0f * logstd[z];
    if (i < OUT_PLANE / 2) {
        int q  = i & 3;
        int l  = (i >> 2) & 31;
        int nP = (i >> 7) & 7;
        int kc = i >> 10;
        int n  = (2 * nP + (q >> 1)) * 8 + (l >> 2);
        int k  = kc * 16 + 2 * (l & 3) + 8 * (q & 1);
        g_epsh[i] = __floats2half2_rn(eps[(size_t)n * MDIM + k], eps[(size_t)n * MDIM + k + 1]);
    }
}

// ---------------------------------------------------------------------------
// 256 CTAs x 192 threads, 2 CTAs per SM.
// warps 0-3: compute; warp = kpar(wid>>1) x nh(wid&1); M32 x N64, C=64 regs.
//            eps fragments LDG'd from L2 via 2-deep register ring.
// warps 4-5: producers — triple-buffered (distance-2) LDG of fp32 B ->
//            cvt fp16 (+fp32 sumsq) -> STS.
// ---------------------------------------------------------------------------
__global__ void __launch_bounds__(192, 2) cov_main(
    const float* __restrict__ B, const float* __restrict__ mu,
    const float* __restrict__ logstd, float* __restrict__ out)
{
    extern __shared__ char smem_raw[];
    const uint32_t raw  = smem_u32(smem_raw);
    const uint32_t base = (raw + 1023u) & ~1023u;
    char* basep = smem_raw + (base - raw);
    float* ssp   = (float*)(basep + SS_OFF);
    float* smemC = (float*)basep;              // reused after main loop (16 KB)

    const int tid  = threadIdx.x;
    const int wid  = tid >> 5;
    const int lane = tid & 31;

    if (tid == 0) {
        #pragma unroll
        for (int s = 0; s < STAGES; s++) {
            MBAR_INIT(base + FULL_OFF  + s * 8, 64);   // 64 producer threads
            MBAR_INIT(base + EMPTY_OFF + s * 8, 2);    // lane0 of 2 consuming warps
        }
    }
    if (tid < MT) ssp[tid] = 0.0f;
    __syncthreads();

    float C[2][8][4];
    const int kpar = wid >> 1;
    const int nh   = wid & 1;
    const int g    = lane >> 2;
    const int tg   = lane & 3;

    if (wid < 4) {
        // ---------------- compute warps ----------------
        const uint32_t rowpat = (uint32_t)((lane & 7) + 8 * ((lane >> 3) & 1));
        const uint32_t swzl   = (uint32_t)(lane & 7) << 4;
        uint32_t aRow[2], colA[4];
        #pragma unroll
        for (int q = 0; q < 2; q++)
            aRow[q] = ((uint32_t)(q * 16) + rowpat) * 128u;
        #pragma unroll
        for (int sk = 0; sk < 4; sk++)
            colA[sk] = ((uint32_t)(sk * 32 + 16 * (lane >> 4))) ^ swzl;

        #pragma unroll
        for (int q = 0; q < 2; q++)
            #pragma unroll
            for (int j = 0; j < 8; j++)
                #pragma unroll
                for (int e = 0; e < 4; e++) C[q][j][e] = 0.0f;

        const uint4* epsp = (const uint4*)g_epsh;
        // eps fragment: idx(kc, jp) = (kc*8 + nh*4 + jp)*32 + lane
        #define EIDX(KC, JP) ((size_t)(((KC) * 8 + nh * 4 + (JP)) * 32 + lane))
        uint4 bb0[4], bb1[4];
        {
            const int kc0 = kpar * 4;
            #pragma unroll
            for (int jp = 0; jp < 4; jp++) bb0[jp] = __ldg(&epsp[EIDX(kc0,     jp)]);
            #pragma unroll
            for (int jp = 0; jp < 4; jp++) bb1[jp] = __ldg(&epsp[EIDX(kc0 + 1, jp)]);
        }

        for (int ti = 0; ti < NITER / 2; ti++) {
            const int it = 2 * ti + kpar;
            const int s  = it & (STAGES - 1);
            const int ph = (it >> 3) & 1;
            MBAR_WAIT(base + FULL_OFF + s * 8, ph);
            const uint32_t stg = base + (uint32_t)s * BT_BYTES;
            const int kc0 = it * 4;
            // prefetch targets for sk = 0..3: next needed kcs at distance 2
            const int pf[4] = { kc0 + 2, kc0 + 3, kc0 + 8, kc0 + 9 };

            #pragma unroll
            for (int sk = 0; sk < 4; sk++) {
                uint4* cur = (sk & 1) ? bb1 : bb0;
                uint32_t a[2][4];
                #pragma unroll
                for (int q = 0; q < 2; q++)
                    LDSM_X4(a[q], stg + aRow[q] + colA[sk]);
                #pragma unroll
                for (int jp = 0; jp < 4; jp++)
                    #pragma unroll
                    for (int q = 0; q < 2; q++) {
                        MMA16(C[q][2 * jp    ], a[q], cur[jp].x, cur[jp].y);
                        MMA16(C[q][2 * jp + 1], a[q], cur[jp].z, cur[jp].w);
                    }
                #pragma unroll
                for (int jp = 0; jp < 4; jp++)
                    cur[jp] = __ldg(&epsp[EIDX(pf[sk], jp)]);
            }
            __syncwarp();
            if (lane == 0) MBAR_ARRIVE(base + EMPTY_OFF + s * 8);
        }
        #undef EIDX
    } else {
        // ---------------- producer warps (64 threads) ----------------
        const int p  = tid - 128;                 // 0..63
        const int rb = p >> 4;                    // base row 0..3
        const int cc = p & 15;                    // 16B fp32 chunk within 256B row
        const float* gB = B + (size_t)blockIdx.x * MT * MDIM;

        float4 bA[8], bB[8], bC[8];
        float ss[8];
        #pragma unroll
        for (int i = 0; i < 8; i++) ss[i] = 0.0f;

        #define P_HANDLE(IT, BUF) do {                                              \
            const int _it = (IT);                                                   \
            const int _s  = _it & (STAGES - 1);                                     \
            const int _ph = ((_it >> 3) & 1) ^ 1;                                   \
            MBAR_WAIT(base + EMPTY_OFF + _s * 8, _ph);                              \
            const float* _src = gB + (size_t)_it * KT + cc * 4;                     \
            _Pragma("unroll")                                                       \
            for (int u = 0; u < 8; u++)                                             \
                (BUF)[u] = *(const float4*)(_src + (size_t)(rb + 4 * u) * MDIM);    \
        } while (0)

        #define P_FLUSH(JT, BUF) do {                                               \
            const int _jt = (JT);                                                   \
            const uint32_t _stgj = base + (uint32_t)(_jt & (STAGES - 1)) * BT_BYTES; \
            _Pragma("unroll")                                                       \
            for (int u = 0; u < 8; u++) {                                           \
                const int _row = rb + 4 * u;                                        \
                float4 _f = (BUF)[u];                                               \
                __half2 _h0 = __floats2half2_rn(_f.x, _f.y);                        \
                __half2 _h1 = __floats2half2_rn(_f.z, _f.w);                        \
                const uint32_t _a = _stgj + (uint32_t)_row * 128u                   \
                    + (((uint32_t)(cc * 8)) ^ ((uint32_t)(_row & 7) << 4));         \
                asm volatile("st.shared.v2.b32 [%0], {%1, %2};"                     \
                    :: "r"(_a), "r"(*(uint32_t*)&_h0), "r"(*(uint32_t*)&_h1) : "memory"); \
                ss[u] = fmaf(_f.x, _f.x, ss[u]);                                    \
                ss[u] = fmaf(_f.y, _f.y, ss[u]);                                    \
                ss[u] = fmaf(_f.z, _f.z, ss[u]);                                    \
                ss[u] = fmaf(_f.w, _f.w, ss[u]);                                    \
            }                                                                       \
            MBAR_ARRIVE(base + FULL_OFF + (_jt & (STAGES - 1)) * 8);                \
        } while (0)

        // distance-2 pipeline: H(k+2) issues before F(k); buffers rotate mod 3
        P_HANDLE(0, bA);
        P_HANDLE(1, bB);
        for (int j = 0; j < (NITER - 2) / 3; j++) {      // 42 iterations -> F(0..125)
            P_HANDLE(3 * j + 2, bC); P_FLUSH(3 * j,     bA);
            P_HANDLE(3 * j + 3, bA); P_FLUSH(3 * j + 1, bB);
            P_HANDLE(3 * j + 4, bB); P_FLUSH(3 * j + 2, bC);
        }
        P_FLUSH(NITER - 2, bA);
        P_FLUSH(NITER - 1, bB);

        // sumsq: reduce over the 16 column-chunk lanes of each row
        #pragma unroll
        for (int u = 0; u < 8; u++) {
            float v = ss[u];
            v += __shfl_xor_sync(0xffffffffu, v, 1);
            v += __shfl_xor_sync(0xffffffffu, v, 2);
            v += __shfl_xor_sync(0xffffffffu, v, 4);
            v += __shfl_xor_sync(0xffffffffu, v, 8);
            if (cc == 0) atomicAdd(&ssp[rb + 4 * u], v);
        }
    }

    __syncthreads();                 // main-loop smem use done; ring reusable

    // kpar 0 warps store C into smemC[col*32 + row]
    if (wid < 2) {
        #pragma unroll
        for (int q = 0; q < 2; q++)
            #pragma unroll
            for (int j = 0; j < 8; j++) {
                int col = nh * 64 + j * 8 + 2 * tg;
                int row = q * 16 + g;
                smemC[(col    ) * 32 + row    ] = C[q][j][0];
                smemC[(col + 1) * 32 + row    ] = C[q][j][1];
                smemC[(col    ) * 32 + row + 8] = C[q][j][2];
                smemC[(col + 1) * 32 + row + 8] = C[q][j][3];
            }
    }
    __syncthreads();
    // kpar 1 warps accumulate
    if (wid >= 2 && wid < 4) {
        #pragma unroll
        for (int q = 0; q < 2; q++)
            #pragma unroll
            for (int j = 0; j < 8; j++) {
                int col = nh * 64 + j * 8 + 2 * tg;
                int row = q * 16 + g;
                smemC[(col    ) * 32 + row    ] += C[q][j][0];
                smemC[(col + 1) * 32 + row    ] += C[q][j][1];
                smemC[(col    ) * 32 + row + 8] += C[q][j][2];
                smemC[(col + 1) * 32 + row + 8] += C[q][j][3];
            }
    }
    __syncthreads();

    if (tid < 128) {
        int m = tid & 31, bq = tid >> 5;          // bq: 0..3, 32 batch cols each
        int mg = blockIdx.x * MT + m, z = mg & (ZDIM - 1);
        float sc  = rsqrtf(ssp[m]) * expf(logstd[z]);
        float muv = mu[z];
        float* op = out + 2 * (size_t)OUT_PLANE + mg;
        #pragma unroll 4
        for (int b = bq * 32; b < bq * 32 + 32; b++)
            op[(size_t)b * MDIM] = fmaf(sc, smemC[b * 32 + m], muv);
    }
}

extern "C" void kernel_launch(void* const* d_in, const int* in_sizes, int n_in,
                              void* d_out, int out_size) {
    const float* mu     = (const float*)d_in[0];
    const float* logstd = (const float*)d_in[1];
    const float* B      = (const float*)d_in[2];
    const float* eps    = (const float*)d_in[3];
    float* out = (float*)d_out;

    cudaFuncSetAttribute(cov_main, cudaFuncAttributeMaxDynamicSharedMemorySize, SMEM_DYN);

    cov_fill<<<(OUT_PLANE + 511) / 512, 512>>>(mu, logstd, eps, out);
    cov_main<<<NCTA, 192, SMEM_DYN>>>(B, mu, logstd, out);
}